// round 14
// baseline (speedup 1.0000x reference)
#include <cuda_runtime.h>
#include <math_constants.h>
#include <cstdint>

#define NSAMPLE 16
#define NPTS    8192
#define BATCH   2
#define CH      64
#define OUTCH   128
#define SEGSZ   4096              // knn candidates per tile (2 tiles per kernel)
#define KBT     256               // knn block threads

typedef unsigned long long ull;
typedef unsigned int uint;
typedef unsigned short ushort;

// ---- f32x2 packed helpers (Blackwell) ----
__device__ __forceinline__ ull pk2(float a, float b) {
    ull r; asm("mov.b64 %0,{%1,%2};" : "=l"(r) : "f"(a), "f"(b)); return r;
}
__device__ __forceinline__ void upk2(float& a, float& b, ull r) {
    asm("mov.b64 {%0,%1}, %2;" : "=f"(a), "=f"(b) : "l"(r));
}
__device__ __forceinline__ ull fma2_(ull a, ull b, ull c) {
    ull d; asm("fma.rn.f32x2 %0,%1,%2,%3;" : "=l"(d) : "l"(a), "l"(b), "l"(c)); return d;
}
__device__ __forceinline__ ull mul2_(ull a, ull b) {
    ull d; asm("mul.rn.f32x2 %0,%1,%2;" : "=l"(d) : "l"(a), "l"(b)); return d;
}
__device__ __forceinline__ float leaky(float x) { return x >= 0.0f ? x : 0.1f * x; }
__device__ __forceinline__ uint umax_(uint a, uint b) { return a > b ? a : b; }

// scratch
__device__ float4 g_pts4[2 * BATCH * NPTS];
__device__ int    g_knn[2 * BATCH * NPTS * NSAMPLE];
__device__ float  g_ms[2 * BATCH * NPTS * CH];
// duplicated-pair MLP weights: g_wD[layer][c][o] = {w[o][c], w[o][c]} (8B each)
__device__ __align__(16) float2 g_w0D[64 * 64];
__device__ __align__(16) float2 g_w1D[64 * 64];

// ---------------------------------------------------------------------------
__global__ void pack_kernel(const float* __restrict__ pc1,
                            const float* __restrict__ pc2) {
    int i = blockIdx.x * blockDim.x + threadIdx.x;
    if (i >= 2 * BATCH * NPTS) return;
    const float* src = (i < BATCH * NPTS) ? pc1 : pc2;
    int r = (i < BATCH * NPTS) ? i : (i - BATCH * NPTS);
    float x = src[r * 3 + 0], y = src[r * 3 + 1], z = src[r * 3 + 2];
    g_pts4[i] = make_float4(x, y, z, x * x + y * y + z * z);
}

// weight prep: transpose + duplicate into float2 pairs (for fma2 broadcast)
__global__ void wprep_kernel(const float* __restrict__ w0,
                             const float* __restrict__ w1) {
    int i = blockIdx.x * blockDim.x + threadIdx.x;   // 0..4095
    if (i >= 4096) return;
    int o = i >> 6, c = i & 63;
    float v0 = w0[i], v1 = w1[i];
    g_w0D[c * 64 + o] = make_float2(v0, v0);
    g_w1D[c * 64 + o] = make_float2(v1, v1);
}

// ---------------------------------------------------------------------------
// KNN (unchanged R13): fused two-tile chained scan, register top-16 carried
// across tiles. uint keys (dist bits | slot), slot-major ushort idx smem,
// 8-candidate batches, shifted threshold, slot bits MASKED on reconstruct.
// ---------------------------------------------------------------------------
__global__ void __launch_bounds__(KBT, 3) knn_kernel() {
    extern __shared__ float ks[];
    float*  sx = ks;
    float*  sy = sx + SEGSZ;
    float*  sz = sy + SEGSZ;
    float*  sw = sz + SEGSZ;
    ushort* sidx = (ushort*)(sw + SEGSZ);    // [16][KBT]

    const int dirb = blockIdx.y;
    const int dir  = dirb >> 1;
    const int b    = dirb & 1;
    const int tid  = threadIdx.x;
    const int n    = blockIdx.x * KBT + tid;
    const size_t q = (size_t)dirb * NPTS + n;

    const float4* Qb = g_pts4 + ((size_t)dir * BATCH + b) * NPTS;
    const float4* Cb0 = g_pts4 + ((size_t)(1 - dir) * BATCH + b) * NPTS;

    uint bk[NSAMPLE];
#pragma unroll
    for (int k = 0; k < NSAMPLE; k++) {
        bk[k] = 0x7F800000u | k;
        sidx[k * KBT + tid] = 0;
    }
    uint wdkey = 0x7F80000Fu;

    const float4 qv = Qb[n];
    const float sq1 = qv.w;
    const ull qx2 = pk2(qv.x, qv.x);
    const ull qy2 = pk2(qv.y, qv.y);
    const ull qz2 = pk2(qv.z, qv.z);
    const ull m2  = pk2(-2.0f, -2.0f);

    float wds = CUDART_INF_F;

#pragma unroll 1
    for (int pass = 0; pass < 2; pass++) {
        const int base = pass * SEGSZ;
        const float4* Cb = Cb0 + base;

        __syncthreads();
        for (int i = tid; i < SEGSZ; i += KBT) {
            float4 c = Cb[i];
            sx[i] = c.x; sy[i] = c.y; sz[i] = c.z; sw[i] = c.w;
        }
        __syncthreads();

#pragma unroll 1
        for (int j = 0; j < SEGSZ; j += 8) {
            ulonglong2 X0 = *reinterpret_cast<const ulonglong2*>(&sx[j]);
            ulonglong2 X1 = *reinterpret_cast<const ulonglong2*>(&sx[j + 4]);
            ulonglong2 Y0 = *reinterpret_cast<const ulonglong2*>(&sy[j]);
            ulonglong2 Y1 = *reinterpret_cast<const ulonglong2*>(&sy[j + 4]);
            ulonglong2 Z0 = *reinterpret_cast<const ulonglong2*>(&sz[j]);
            ulonglong2 Z1 = *reinterpret_cast<const ulonglong2*>(&sz[j + 4]);
            ulonglong2 W0 = *reinterpret_cast<const ulonglong2*>(&sw[j]);
            ulonglong2 W1 = *reinterpret_cast<const ulonglong2*>(&sw[j + 4]);

            ull t0 = fma2_(qx2, X0.x, fma2_(qy2, Y0.x, mul2_(qz2, Z0.x)));
            ull t1 = fma2_(qx2, X0.y, fma2_(qy2, Y0.y, mul2_(qz2, Z0.y)));
            ull t2 = fma2_(qx2, X1.x, fma2_(qy2, Y1.x, mul2_(qz2, Z1.x)));
            ull t3 = fma2_(qx2, X1.y, fma2_(qy2, Y1.y, mul2_(qz2, Z1.y)));
            ull s01 = fma2_(m2, t0, W0.x);
            ull s23 = fma2_(m2, t1, W0.y);
            ull s45 = fma2_(m2, t2, W1.x);
            ull s67 = fma2_(m2, t3, W1.y);

            float s[8];
            upk2(s[0], s[1], s01);
            upk2(s[2], s[3], s23);
            upk2(s[4], s[5], s45);
            upk2(s[6], s[7], s67);

            float m4a = fminf(fminf(s[0], s[1]), fminf(s[2], s[3]));
            float m4b = fminf(fminf(s[4], s[5]), fminf(s[6], s[7]));
            float m8  = fminf(m4a, m4b);

            if (m8 < wds) {
#pragma unroll
                for (int g = 0; g < 2; g++) {
                    float mg = g ? m4b : m4a;
                    if (mg < wds) {
#pragma unroll
                        for (int t = 0; t < 4; t++) {
                            float sv = s[g * 4 + t];
                            if (sv < wds) {
                                float d = sv + sq1;
                                uint slot = wdkey & 15u;
                                uint nk = (__float_as_uint(fmaxf(d, 0.0f)) & 0xFFFFFFF0u) | slot;
                                sidx[slot * KBT + tid] = (ushort)(base + j + g * 4 + t);
#pragma unroll
                                for (int k = 0; k < NSAMPLE; k++)
                                    bk[k] = (bk[k] == wdkey) ? nk : bk[k];
                                uint m0[8];
#pragma unroll
                                for (int k = 0; k < 8; k++) m0[k] = umax_(bk[2*k], bk[2*k+1]);
                                uint m1[4];
#pragma unroll
                                for (int k = 0; k < 4; k++) m1[k] = umax_(m0[2*k], m0[2*k+1]);
                                wdkey = umax_(umax_(m1[0], m1[1]), umax_(m1[2], m1[3]));
                                wds = __uint_as_float(wdkey & 0xFFFFFFF0u) - sq1;
                            }
                        }
                    }
                }
            }
        }
    }

    int* outp = g_knn + q * NSAMPLE;
#pragma unroll
    for (int k = 0; k < NSAMPLE; k++)
        outp[k] = (int)sidx[(bk[k] & 15u) * KBT + tid];
}

// ---------------------------------------------------------------------------
// feat v3: activations transposed in smem [p][c][k] (KSTR=18 pad, all k-pair
// loads 8B aligned). f32x2 pairs run along k; weights pre-duplicated in
// global float2 (L1). Zero per-MAC MOV dups. acc[o(8)][kpair(4)].
// ---------------------------------------------------------------------------
#define KSTR 18
#define PSTR (64 * KSTR)          // 1152 floats per point

__global__ void __launch_bounds__(128, 4) feat_kernel(
        const float* __restrict__ feat1,
        const float* __restrict__ feat2,
        const float* __restrict__ pos_w,
        const float* __restrict__ pos_b,
        const float* __restrict__ b0,
        const float* __restrict__ b1) {
    extern __shared__ float sm[];
    float* hs    = sm;                         // 8*1152 = 9216
    float* pm    = hs;                         // ALIAS: hs dead after layer 2
    float* posws = hs + 8 * PSTR;              // 192
    float* posbs = posws + 192;                // 64
    float* b0s   = posbs + 64;                 // 64
    float* b1s   = b0s + 64;                   // 64

    const int dir = blockIdx.z;
    const int b   = blockIdx.y;
    const int tid = threadIdx.x;
    const int dirb = dir * BATCH + b;

    if (tid < 64) {
        posbs[tid] = pos_b[tid];
        b0s[tid]   = b0[tid];
        b1s[tid]   = b1[tid];
    }
    for (int i = tid; i < 192; i += 128) posws[i] = pos_w[i];
    __syncthreads();

    const float* F1 = dir ? feat2 : feat1;
    const float* F2 = dir ? feat1 : feat2;
    const float4* QC = g_pts4 + ((size_t)dir * BATCH + b) * NPTS;
    const float4* NC = g_pts4 + ((size_t)(1 - dir) * BATCH + b) * NPTS;

    // ---- stage 1: gather + pos feat + leaky -> hs[p][c][k] (transposed) ----
    {
        const int c  = tid & 63;
        const int rh = tid >> 6;
        const float pwx = posws[c * 3 + 0];
        const float pwy = posws[c * 3 + 1];
        const float pwz = posws[c * 3 + 2];
        const float pb  = posbs[c];
        for (int it = 0; it < 64; it++) {
            int row = it * 2 + rh;
            int p = row >> 4, k = row & 15;
            int n = blockIdx.x * 8 + p;
            int id = g_knn[((size_t)dirb * NPTS + n) * NSAMPLE + k];
            float4 cc = NC[id];
            float4 qq = QC[n];
            float g   = F2[((size_t)b * NPTS + id) * CH + c];
            float p1o = F1[((size_t)b * NPTS + n) * CH + c];
            float h = g + p1o +
                fmaf(pwx, cc.x - qq.x, fmaf(pwy, cc.y - qq.y,
                fmaf(pwz, cc.z - qq.z, pb)));
            hs[p * PSTR + c * KSTR + k] = leaky(h);
        }
    }
    __syncthreads();

    const int tt = tid & 15;
    const int p  = tid >> 4;
    const int o0 = (tt & 7) * 8;
    const int k0 = (tt >> 3) * 8;
    float* hpb = hs + p * PSTR + k0;          // + c*KSTR inside loops

    ull acc[8][4];   // [oi][kpair]

    // =============== layer 1 ===============
    {
#pragma unroll
        for (int oi = 0; oi < 8; oi++) {
            ull bb = pk2(b0s[o0 + oi], b0s[o0 + oi]);
            acc[oi][0] = bb; acc[oi][1] = bb; acc[oi][2] = bb; acc[oi][3] = bb;
        }
#pragma unroll 1
        for (int c = 0; c < 64; c += 4) {
#pragma unroll
            for (int cc = 0; cc < 4; cc++) {
                const ull* wp = (const ull*)g_w0D + (c + cc) * 64 + o0;
                ulonglong2 wA = *(const ulonglong2*)(wp);
                ulonglong2 wB = *(const ulonglong2*)(wp + 2);
                ulonglong2 wC = *(const ulonglong2*)(wp + 4);
                ulonglong2 wD = *(const ulonglong2*)(wp + 6);
                const ull* hp = (const ull*)(hpb + (c + cc) * KSTR);
                ull h0 = hp[0], h1 = hp[1], h2 = hp[2], h3 = hp[3];
                ull warr[8] = {wA.x, wA.y, wB.x, wB.y, wC.x, wC.y, wD.x, wD.y};
#pragma unroll
                for (int oi = 0; oi < 8; oi++) {
                    acc[oi][0] = fma2_(h0, warr[oi], acc[oi][0]);
                    acc[oi][1] = fma2_(h1, warr[oi], acc[oi][1]);
                    acc[oi][2] = fma2_(h2, warr[oi], acc[oi][2]);
                    acc[oi][3] = fma2_(h3, warr[oi], acc[oi][3]);
                }
            }
        }
    }
    __syncthreads();
    // leaky + writeback: output o becomes layer-2 input c -> hs[p][o][k]
#pragma unroll
    for (int oi = 0; oi < 8; oi++) {
        float* dst = hs + p * PSTR + (o0 + oi) * KSTR + k0;
#pragma unroll
        for (int kp = 0; kp < 4; kp++) {
            float lo, hi;
            upk2(lo, hi, acc[oi][kp]);
            *(ull*)(dst + 2 * kp) = pk2(leaky(lo), leaky(hi));
        }
    }
    __syncthreads();

    // =============== layer 2 ===============
    {
#pragma unroll
        for (int oi = 0; oi < 8; oi++) {
            ull bb = pk2(b1s[o0 + oi], b1s[o0 + oi]);
            acc[oi][0] = bb; acc[oi][1] = bb; acc[oi][2] = bb; acc[oi][3] = bb;
        }
#pragma unroll 1
        for (int c = 0; c < 64; c += 4) {
#pragma unroll
            for (int cc = 0; cc < 4; cc++) {
                const ull* wp = (const ull*)g_w1D + (c + cc) * 64 + o0;
                ulonglong2 wA = *(const ulonglong2*)(wp);
                ulonglong2 wB = *(const ulonglong2*)(wp + 2);
                ulonglong2 wC = *(const ulonglong2*)(wp + 4);
                ulonglong2 wD = *(const ulonglong2*)(wp + 6);
                const ull* hp = (const ull*)(hpb + (c + cc) * KSTR);
                ull h0 = hp[0], h1 = hp[1], h2 = hp[2], h3 = hp[3];
                ull warr[8] = {wA.x, wA.y, wB.x, wB.y, wC.x, wC.y, wD.x, wD.y};
#pragma unroll
                for (int oi = 0; oi < 8; oi++) {
                    acc[oi][0] = fma2_(h0, warr[oi], acc[oi][0]);
                    acc[oi][1] = fma2_(h1, warr[oi], acc[oi][1]);
                    acc[oi][2] = fma2_(h2, warr[oi], acc[oi][2]);
                    acc[oi][3] = fma2_(h3, warr[oi], acc[oi][3]);
                }
            }
        }
    }

    __syncthreads();   // hs dead; pm aliases it

    // leaky + max over this thread's 8 k (4 pairs) per output channel
    {
        float mx[8];
#pragma unroll
        for (int oi = 0; oi < 8; oi++) {
            float m = -CUDART_INF_F;
#pragma unroll
            for (int kp = 0; kp < 4; kp++) {
                float lo, hi;
                upk2(lo, hi, acc[oi][kp]);
                m = fmaxf(m, fmaxf(leaky(lo), leaky(hi)));
            }
            mx[oi] = m;
        }
        float* pmp = pm + p * 128 + (k0 >> 3) * 64 + o0;
        *reinterpret_cast<float4*>(pmp)     = make_float4(mx[0], mx[1], mx[2], mx[3]);
        *reinterpret_cast<float4*>(pmp + 4) = make_float4(mx[4], mx[5], mx[6], mx[7]);
    }
    __syncthreads();

#pragma unroll
    for (int i = 0; i < 4; i++) {
        int ii = tid + i * 128;
        int pp = ii >> 6, oo = ii & 63;
        float mm = fmaxf(pm[pp * 128 + oo], pm[pp * 128 + 64 + oo]);
        int nn = blockIdx.x * 8 + pp;
        g_ms[((size_t)dirb * NPTS + nn) * CH + oo] = mm;
    }
}

// ---------------------------------------------------------------------------
// proj (unchanged)
// ---------------------------------------------------------------------------
#define PPROJ 64
__global__ void __launch_bounds__(128) proj_kernel(
        const float* __restrict__ t1w, const float* __restrict__ t1b,
        const float* __restrict__ t2w, const float* __restrict__ t2b,
        float* __restrict__ out) {
    __shared__ float aS[PPROJ * 64];

    const int dir = blockIdx.z;
    const int b   = blockIdx.y;
    const int j   = threadIdx.x;
    const int dirb = dir * BATCH + b;

    const float* tw = dir ? t2w : t1w;
    const float* tb = dir ? t2b : t1b;

    float4 w[16];
#pragma unroll
    for (int t = 0; t < 16; t++)
        w[t] = reinterpret_cast<const float4*>(tw + j * 64)[t];
    const float bias = tb[j];

    const int n0 = blockIdx.x * PPROJ;
#pragma unroll
    for (int i = 0; i < PPROJ * 64 / 128 / 4; i++) {
        int f = j + i * 128;
        reinterpret_cast<float4*>(aS)[f] =
            reinterpret_cast<const float4*>(g_ms + ((size_t)dirb * NPTS + n0) * CH)[f];
    }
    __syncthreads();

#pragma unroll 2
    for (int p = 0; p < PPROJ; p++) {
        float acc = bias;
        const float4* ap = reinterpret_cast<const float4*>(aS + p * 64);
#pragma unroll
        for (int t = 0; t < 16; t++) {
            float4 a = ap[t];
            acc = fmaf(a.x, w[t].x, acc);
            acc = fmaf(a.y, w[t].y, acc);
            acc = fmaf(a.z, w[t].z, acc);
            acc = fmaf(a.w, w[t].w, acc);
        }
        out[((size_t)dirb * NPTS + n0 + p) * OUTCH + j] = acc;
    }
}

// ---------------------------------------------------------------------------
extern "C" void kernel_launch(void* const* d_in, const int* in_sizes, int n_in,
                              void* d_out, int out_size) {
    (void)in_sizes; (void)n_in; (void)out_size;
    const float* pc1   = (const float*)d_in[0];
    const float* pc2   = (const float*)d_in[1];
    const float* feat1 = (const float*)d_in[2];
    const float* feat2 = (const float*)d_in[3];
    const float* pos_w = (const float*)d_in[4];
    const float* pos_b = (const float*)d_in[5];
    const float* w0    = (const float*)d_in[6];
    const float* b0    = (const float*)d_in[7];
    const float* w1    = (const float*)d_in[8];
    const float* b1    = (const float*)d_in[9];
    const float* t1w   = (const float*)d_in[10];
    const float* t1b   = (const float*)d_in[11];
    const float* t2w   = (const float*)d_in[12];
    const float* t2b   = (const float*)d_in[13];
    float* out = (float*)d_out;

    pack_kernel<<<(2 * BATCH * NPTS + 255) / 256, 256>>>(pc1, pc2);
    wprep_kernel<<<16, 256>>>(w0, w1);

    const size_t ksmem = 4 * SEGSZ * sizeof(float) + NSAMPLE * KBT * sizeof(ushort);
    cudaFuncSetAttribute(knn_kernel,
                         cudaFuncAttributeMaxDynamicSharedMemorySize, (int)ksmem);
    dim3 gk(NPTS / KBT, 2 * BATCH);
    knn_kernel<<<gk, KBT, ksmem>>>();

    const size_t smem = (size_t)(8 * PSTR + 192 + 64 * 3) * sizeof(float);
    cudaFuncSetAttribute(feat_kernel,
                         cudaFuncAttributeMaxDynamicSharedMemorySize, (int)smem);
    dim3 gf(NPTS / 8, BATCH, 2);
    feat_kernel<<<gf, 128, smem>>>(feat1, feat2, pos_w, pos_b, b0, b1);

    dim3 gp(NPTS / PPROJ, BATCH, 2);
    proj_kernel<<<gp, 128>>>(t1w, t1b, t2w, t2b, out);
}

// round 15
// speedup vs baseline: 1.4126x; 1.4126x over previous
#include <cuda_runtime.h>
#include <math_constants.h>
#include <cstdint>

#define NSAMPLE 16
#define NPTS    8192
#define BATCH   2
#define CH      64
#define OUTCH   128
#define SEGSZ   4096              // knn candidates per tile (2 tiles per kernel)
#define KBT     128               // knn block threads (256 blocks -> all SMs)

typedef unsigned long long ull;
typedef unsigned int uint;
typedef unsigned short ushort;

// ---- f32x2 packed helpers (Blackwell) ----
__device__ __forceinline__ ull pk2(float a, float b) {
    ull r; asm("mov.b64 %0,{%1,%2};" : "=l"(r) : "f"(a), "f"(b)); return r;
}
__device__ __forceinline__ void upk2(float& a, float& b, ull r) {
    asm("mov.b64 {%0,%1}, %2;" : "=f"(a), "=f"(b) : "l"(r));
}
__device__ __forceinline__ ull fma2_(ull a, ull b, ull c) {
    ull d; asm("fma.rn.f32x2 %0,%1,%2,%3;" : "=l"(d) : "l"(a), "l"(b), "l"(c)); return d;
}
__device__ __forceinline__ ull mul2_(ull a, ull b) {
    ull d; asm("mul.rn.f32x2 %0,%1,%2;" : "=l"(d) : "l"(a), "l"(b)); return d;
}
__device__ __forceinline__ float leaky(float x) { return x >= 0.0f ? x : 0.1f * x; }
__device__ __forceinline__ uint umax_(uint a, uint b) { return a > b ? a : b; }

#define WSTR 68

// scratch
__device__ float4 g_pts4[2 * BATCH * NPTS];
__device__ int    g_knn[2 * BATCH * NPTS * NSAMPLE];
__device__ __align__(16) float g_w0T[64 * WSTR];
__device__ __align__(16) float g_w1T[64 * WSTR];

// ---------------------------------------------------------------------------
__global__ void pack_kernel(const float* __restrict__ pc1,
                            const float* __restrict__ pc2) {
    int i = blockIdx.x * blockDim.x + threadIdx.x;
    if (i >= 2 * BATCH * NPTS) return;
    const float* src = (i < BATCH * NPTS) ? pc1 : pc2;
    int r = (i < BATCH * NPTS) ? i : (i - BATCH * NPTS);
    float x = src[r * 3 + 0], y = src[r * 3 + 1], z = src[r * 3 + 2];
    g_pts4[i] = make_float4(x, y, z, x * x + y * y + z * z);
}

__global__ void wprep_kernel(const float* __restrict__ w0,
                             const float* __restrict__ w1) {
    int f = blockIdx.x * blockDim.x + threadIdx.x;   // float4 index, 1024 total
    if (f >= 1024) return;
    float4 a = reinterpret_cast<const float4*>(w0)[f];
    float4 c = reinterpret_cast<const float4*>(w1)[f];
    int o = f >> 4, c0 = (f & 15) * 4;
    g_w0T[(c0 + 0) * WSTR + o] = a.x;
    g_w0T[(c0 + 1) * WSTR + o] = a.y;
    g_w0T[(c0 + 2) * WSTR + o] = a.z;
    g_w0T[(c0 + 3) * WSTR + o] = a.w;
    g_w1T[(c0 + 0) * WSTR + o] = c.x;
    g_w1T[(c0 + 1) * WSTR + o] = c.y;
    g_w1T[(c0 + 2) * WSTR + o] = c.z;
    g_w1T[(c0 + 3) * WSTR + o] = c.w;
}

// ---------------------------------------------------------------------------
// KNN (R13 body, KBT=128): fused two-tile chained scan, register top-16
// carried across tiles. uint keys (dist bits | slot), slot-major ushort idx
// smem, 8-candidate batches, shifted threshold, slot bits MASKED.
// ---------------------------------------------------------------------------
__global__ void __launch_bounds__(KBT, 3) knn_kernel() {
    extern __shared__ float ks[];
    float*  sx = ks;
    float*  sy = sx + SEGSZ;
    float*  sz = sy + SEGSZ;
    float*  sw = sz + SEGSZ;
    ushort* sidx = (ushort*)(sw + SEGSZ);    // [16][KBT]

    const int dirb = blockIdx.y;
    const int dir  = dirb >> 1;
    const int b    = dirb & 1;
    const int tid  = threadIdx.x;
    const int n    = blockIdx.x * KBT + tid;
    const size_t q = (size_t)dirb * NPTS + n;

    const float4* Qb = g_pts4 + ((size_t)dir * BATCH + b) * NPTS;
    const float4* Cb0 = g_pts4 + ((size_t)(1 - dir) * BATCH + b) * NPTS;

    uint bk[NSAMPLE];
#pragma unroll
    for (int k = 0; k < NSAMPLE; k++) {
        bk[k] = 0x7F800000u | k;
        sidx[k * KBT + tid] = 0;
    }
    uint wdkey = 0x7F80000Fu;

    const float4 qv = Qb[n];
    const float sq1 = qv.w;
    const ull qx2 = pk2(qv.x, qv.x);
    const ull qy2 = pk2(qv.y, qv.y);
    const ull qz2 = pk2(qv.z, qv.z);
    const ull m2  = pk2(-2.0f, -2.0f);

    float wds = CUDART_INF_F;

#pragma unroll 1
    for (int pass = 0; pass < 2; pass++) {
        const int base = pass * SEGSZ;
        const float4* Cb = Cb0 + base;

        __syncthreads();
        for (int i = tid; i < SEGSZ; i += KBT) {
            float4 c = Cb[i];
            sx[i] = c.x; sy[i] = c.y; sz[i] = c.z; sw[i] = c.w;
        }
        __syncthreads();

#pragma unroll 1
        for (int j = 0; j < SEGSZ; j += 8) {
            ulonglong2 X0 = *reinterpret_cast<const ulonglong2*>(&sx[j]);
            ulonglong2 X1 = *reinterpret_cast<const ulonglong2*>(&sx[j + 4]);
            ulonglong2 Y0 = *reinterpret_cast<const ulonglong2*>(&sy[j]);
            ulonglong2 Y1 = *reinterpret_cast<const ulonglong2*>(&sy[j + 4]);
            ulonglong2 Z0 = *reinterpret_cast<const ulonglong2*>(&sz[j]);
            ulonglong2 Z1 = *reinterpret_cast<const ulonglong2*>(&sz[j + 4]);
            ulonglong2 W0 = *reinterpret_cast<const ulonglong2*>(&sw[j]);
            ulonglong2 W1 = *reinterpret_cast<const ulonglong2*>(&sw[j + 4]);

            ull t0 = fma2_(qx2, X0.x, fma2_(qy2, Y0.x, mul2_(qz2, Z0.x)));
            ull t1 = fma2_(qx2, X0.y, fma2_(qy2, Y0.y, mul2_(qz2, Z0.y)));
            ull t2 = fma2_(qx2, X1.x, fma2_(qy2, Y1.x, mul2_(qz2, Z1.x)));
            ull t3 = fma2_(qx2, X1.y, fma2_(qy2, Y1.y, mul2_(qz2, Z1.y)));
            ull s01 = fma2_(m2, t0, W0.x);
            ull s23 = fma2_(m2, t1, W0.y);
            ull s45 = fma2_(m2, t2, W1.x);
            ull s67 = fma2_(m2, t3, W1.y);

            float s[8];
            upk2(s[0], s[1], s01);
            upk2(s[2], s[3], s23);
            upk2(s[4], s[5], s45);
            upk2(s[6], s[7], s67);

            float m4a = fminf(fminf(s[0], s[1]), fminf(s[2], s[3]));
            float m4b = fminf(fminf(s[4], s[5]), fminf(s[6], s[7]));
            float m8  = fminf(m4a, m4b);

            if (m8 < wds) {
#pragma unroll
                for (int g = 0; g < 2; g++) {
                    float mg = g ? m4b : m4a;
                    if (mg < wds) {
#pragma unroll
                        for (int t = 0; t < 4; t++) {
                            float sv = s[g * 4 + t];
                            if (sv < wds) {
                                float d = sv + sq1;
                                uint slot = wdkey & 15u;
                                uint nk = (__float_as_uint(fmaxf(d, 0.0f)) & 0xFFFFFFF0u) | slot;
                                sidx[slot * KBT + tid] = (ushort)(base + j + g * 4 + t);
#pragma unroll
                                for (int k = 0; k < NSAMPLE; k++)
                                    bk[k] = (bk[k] == wdkey) ? nk : bk[k];
                                uint m0[8];
#pragma unroll
                                for (int k = 0; k < 8; k++) m0[k] = umax_(bk[2*k], bk[2*k+1]);
                                uint m1[4];
#pragma unroll
                                for (int k = 0; k < 4; k++) m1[k] = umax_(m0[2*k], m0[2*k+1]);
                                wdkey = umax_(umax_(m1[0], m1[1]), umax_(m1[2], m1[3]));
                                wds = __uint_as_float(wdkey & 0xFFFFFFF0u) - sq1;
                            }
                        }
                    }
                }
            }
        }
    }

    int* outp = g_knn + q * NSAMPLE;
#pragma unroll
    for (int k = 0; k < NSAMPLE; k++)
        outp[k] = (int)sidx[(bk[k] & 15u) * KBT + tid];
}

// ---------------------------------------------------------------------------
// feat (R13 core) + fused projection epilogue. 128 threads = 8 pts x 16 thr;
// k8 x o8 f32x2 tiles; weights from pre-transposed global (L1); pm/ms2 alias
// hs. Epilogue: thread = output channel j, per-point broadcast LDS of ms2,
// t-weight row in registers (loaded after MMA accs die). Writes out directly.
// ---------------------------------------------------------------------------
#define HROWS 68
#define HPNT  1128

__device__ __forceinline__ int hoff(int p, int k) {
    return p * HPNT + k * HROWS + ((k >> 3) << 4);
}

__global__ void __launch_bounds__(128, 4) feat_kernel(
        const float* __restrict__ feat1,
        const float* __restrict__ feat2,
        const float* __restrict__ pos_w,
        const float* __restrict__ pos_b,
        const float* __restrict__ b0,
        const float* __restrict__ b1,
        const float* __restrict__ t1w,
        const float* __restrict__ t1b,
        const float* __restrict__ t2w,
        const float* __restrict__ t2b,
        float* __restrict__ out) {
    extern __shared__ float sm[];
    float* hs    = sm;                         // 9024
    float* pm    = hs;                         // ALIAS: hs dead after layer 2
    float* ms2   = hs + 1024;                  // 512 (per-point max, 8x64)
    float* posws = hs + 8 * HPNT;              // 192
    float* posbs = posws + 192;                // 64
    float* b0s   = posbs + 64;                 // 64
    float* b1s   = b0s + 64;                   // 64

    const int dir = blockIdx.z;
    const int b   = blockIdx.y;
    const int tid = threadIdx.x;
    const int dirb = dir * BATCH + b;

    if (tid < 64) {
        posbs[tid] = pos_b[tid];
        b0s[tid]   = b0[tid];
        b1s[tid]   = b1[tid];
    }
    for (int i = tid; i < 192; i += 128) posws[i] = pos_w[i];
    __syncthreads();

    const float* F1 = dir ? feat2 : feat1;
    const float* F2 = dir ? feat1 : feat2;
    const float4* QC = g_pts4 + ((size_t)dir * BATCH + b) * NPTS;
    const float4* NC = g_pts4 + ((size_t)(1 - dir) * BATCH + b) * NPTS;

    // ---- stage 1: gather + pos feat + leaky -> hs ----
    {
        const int c  = tid & 63;
        const int rh = tid >> 6;
        const float pwx = posws[c * 3 + 0];
        const float pwy = posws[c * 3 + 1];
        const float pwz = posws[c * 3 + 2];
        const float pb  = posbs[c];
        for (int it = 0; it < 64; it++) {
            int row = it * 2 + rh;
            int p = row >> 4, k = row & 15;
            int n = blockIdx.x * 8 + p;
            int id = g_knn[((size_t)dirb * NPTS + n) * NSAMPLE + k];
            float4 cc = NC[id];
            float4 qq = QC[n];
            float g   = F2[((size_t)b * NPTS + id) * CH + c];
            float p1o = F1[((size_t)b * NPTS + n) * CH + c];
            float h = g + p1o +
                fmaf(pwx, cc.x - qq.x, fmaf(pwy, cc.y - qq.y,
                fmaf(pwz, cc.z - qq.z, pb)));
            hs[hoff(p, k) + c] = leaky(h);
        }
    }
    __syncthreads();

    const int tt = tid & 15;
    const int p  = tid >> 4;
    const int o0 = (tt & 7) * 8;
    const int k0 = (tt >> 3) * 8;
    float* hp2 = hs + hoff(p, k0);

    ull acc[8][4];

    // =============== layer 1 ===============
    {
        ulonglong2 bA = *reinterpret_cast<const ulonglong2*>(b0s + o0);
        ulonglong2 bB = *reinterpret_cast<const ulonglong2*>(b0s + o0 + 4);
#pragma unroll
        for (int ki = 0; ki < 8; ki++) {
            acc[ki][0] = bA.x; acc[ki][1] = bA.y;
            acc[ki][2] = bB.x; acc[ki][3] = bB.y;
        }
#pragma unroll 1
        for (int c = 0; c < 64; c += 4) {
            const float* wp = g_w0T + c * WSTR + o0;
            ulonglong2 wa0 = *reinterpret_cast<const ulonglong2*>(wp);
            ulonglong2 wa1 = *reinterpret_cast<const ulonglong2*>(wp + 4);
            ulonglong2 wb0 = *reinterpret_cast<const ulonglong2*>(wp + WSTR);
            ulonglong2 wb1 = *reinterpret_cast<const ulonglong2*>(wp + WSTR + 4);
            ulonglong2 wc0 = *reinterpret_cast<const ulonglong2*>(wp + 2 * WSTR);
            ulonglong2 wc1 = *reinterpret_cast<const ulonglong2*>(wp + 2 * WSTR + 4);
            ulonglong2 wd0 = *reinterpret_cast<const ulonglong2*>(wp + 3 * WSTR);
            ulonglong2 wd1 = *reinterpret_cast<const ulonglong2*>(wp + 3 * WSTR + 4);
#pragma unroll
            for (int ki = 0; ki < 8; ki++) {
                float4 hv = *reinterpret_cast<const float4*>(hp2 + ki * HROWS + c);
                ull h0 = pk2(hv.x, hv.x);
                ull h1 = pk2(hv.y, hv.y);
                ull h2 = pk2(hv.z, hv.z);
                ull h3 = pk2(hv.w, hv.w);
                acc[ki][0] = fma2_(h0, wa0.x, acc[ki][0]);
                acc[ki][1] = fma2_(h0, wa0.y, acc[ki][1]);
                acc[ki][2] = fma2_(h0, wa1.x, acc[ki][2]);
                acc[ki][3] = fma2_(h0, wa1.y, acc[ki][3]);
                acc[ki][0] = fma2_(h1, wb0.x, acc[ki][0]);
                acc[ki][1] = fma2_(h1, wb0.y, acc[ki][1]);
                acc[ki][2] = fma2_(h1, wb1.x, acc[ki][2]);
                acc[ki][3] = fma2_(h1, wb1.y, acc[ki][3]);
                acc[ki][0] = fma2_(h2, wc0.x, acc[ki][0]);
                acc[ki][1] = fma2_(h2, wc0.y, acc[ki][1]);
                acc[ki][2] = fma2_(h2, wc1.x, acc[ki][2]);
                acc[ki][3] = fma2_(h2, wc1.y, acc[ki][3]);
                acc[ki][0] = fma2_(h3, wd0.x, acc[ki][0]);
                acc[ki][1] = fma2_(h3, wd0.y, acc[ki][1]);
                acc[ki][2] = fma2_(h3, wd1.x, acc[ki][2]);
                acc[ki][3] = fma2_(h3, wd1.y, acc[ki][3]);
            }
        }
    }
    __syncthreads();
#pragma unroll
    for (int ki = 0; ki < 8; ki++) {
        float a0, a1, a2, a3, a4, a5, a6, a7;
        upk2(a0, a1, acc[ki][0]);
        upk2(a2, a3, acc[ki][1]);
        upk2(a4, a5, acc[ki][2]);
        upk2(a6, a7, acc[ki][3]);
        float4 v0 = make_float4(leaky(a0), leaky(a1), leaky(a2), leaky(a3));
        float4 v1 = make_float4(leaky(a4), leaky(a5), leaky(a6), leaky(a7));
        *reinterpret_cast<float4*>(hp2 + ki * HROWS + o0)     = v0;
        *reinterpret_cast<float4*>(hp2 + ki * HROWS + o0 + 4) = v1;
    }
    __syncthreads();

    // =============== layer 2 ===============
    {
        ulonglong2 bA = *reinterpret_cast<const ulonglong2*>(b1s + o0);
        ulonglong2 bB = *reinterpret_cast<const ulonglong2*>(b1s + o0 + 4);
#pragma unroll
        for (int ki = 0; ki < 8; ki++) {
            acc[ki][0] = bA.x; acc[ki][1] = bA.y;
            acc[ki][2] = bB.x; acc[ki][3] = bB.y;
        }
#pragma unroll 1
        for (int c = 0; c < 64; c += 4) {
            const float* wp = g_w1T + c * WSTR + o0;
            ulonglong2 wa0 = *reinterpret_cast<const ulonglong2*>(wp);
            ulonglong2 wa1 = *reinterpret_cast<const ulonglong2*>(wp + 4);
            ulonglong2 wb0 = *reinterpret_cast<const ulonglong2*>(wp + WSTR);
            ulonglong2 wb1 = *reinterpret_cast<const ulonglong2*>(wp + WSTR + 4);
            ulonglong2 wc0 = *reinterpret_cast<const ulonglong2*>(wp + 2 * WSTR);
            ulonglong2 wc1 = *reinterpret_cast<const ulonglong2*>(wp + 2 * WSTR + 4);
            ulonglong2 wd0 = *reinterpret_cast<const ulonglong2*>(wp + 3 * WSTR);
            ulonglong2 wd1 = *reinterpret_cast<const ulonglong2*>(wp + 3 * WSTR + 4);
#pragma unroll
            for (int ki = 0; ki < 8; ki++) {
                float4 hv = *reinterpret_cast<const float4*>(hp2 + ki * HROWS + c);
                ull h0 = pk2(hv.x, hv.x);
                ull h1 = pk2(hv.y, hv.y);
                ull h2 = pk2(hv.z, hv.z);
                ull h3 = pk2(hv.w, hv.w);
                acc[ki][0] = fma2_(h0, wa0.x, acc[ki][0]);
                acc[ki][1] = fma2_(h0, wa0.y, acc[ki][1]);
                acc[ki][2] = fma2_(h0, wa1.x, acc[ki][2]);
                acc[ki][3] = fma2_(h0, wa1.y, acc[ki][3]);
                acc[ki][0] = fma2_(h1, wb0.x, acc[ki][0]);
                acc[ki][1] = fma2_(h1, wb0.y, acc[ki][1]);
                acc[ki][2] = fma2_(h1, wb1.x, acc[ki][2]);
                acc[ki][3] = fma2_(h1, wb1.y, acc[ki][3]);
                acc[ki][0] = fma2_(h2, wc0.x, acc[ki][0]);
                acc[ki][1] = fma2_(h2, wc0.y, acc[ki][1]);
                acc[ki][2] = fma2_(h2, wc1.x, acc[ki][2]);
                acc[ki][3] = fma2_(h2, wc1.y, acc[ki][3]);
                acc[ki][0] = fma2_(h3, wd0.x, acc[ki][0]);
                acc[ki][1] = fma2_(h3, wd0.y, acc[ki][1]);
                acc[ki][2] = fma2_(h3, wd1.x, acc[ki][2]);
                acc[ki][3] = fma2_(h3, wd1.y, acc[ki][3]);
            }
        }
    }

    __syncthreads();   // hs dead; pm/ms2 alias it

    {
        float mx[8];
#pragma unroll
        for (int j = 0; j < 8; j++) mx[j] = -CUDART_INF_F;
#pragma unroll
        for (int ki = 0; ki < 8; ki++) {
            float a0, a1, a2, a3, a4, a5, a6, a7;
            upk2(a0, a1, acc[ki][0]);
            upk2(a2, a3, acc[ki][1]);
            upk2(a4, a5, acc[ki][2]);
            upk2(a6, a7, acc[ki][3]);
            mx[0] = fmaxf(mx[0], leaky(a0));
            mx[1] = fmaxf(mx[1], leaky(a1));
            mx[2] = fmaxf(mx[2], leaky(a2));
            mx[3] = fmaxf(mx[3], leaky(a3));
            mx[4] = fmaxf(mx[4], leaky(a4));
            mx[5] = fmaxf(mx[5], leaky(a5));
            mx[6] = fmaxf(mx[6], leaky(a6));
            mx[7] = fmaxf(mx[7], leaky(a7));
        }
        float* pmp = pm + p * 128 + (k0 >> 3) * 64 + o0;
        *reinterpret_cast<float4*>(pmp)     = make_float4(mx[0], mx[1], mx[2], mx[3]);
        *reinterpret_cast<float4*>(pmp + 4) = make_float4(mx[4], mx[5], mx[6], mx[7]);
    }
    __syncthreads();

    // final max of 2 k-halves -> ms2[8][64]
#pragma unroll
    for (int i = 0; i < 4; i++) {
        int ii = tid + i * 128;
        int pp = ii >> 6, oo = ii & 63;
        ms2[pp * 64 + oo] = fmaxf(pm[pp * 128 + oo], pm[pp * 128 + 64 + oo]);
    }
    __syncthreads();

    // ---- fused projection: thread = output channel j, 8 points ----
    {
        const float* tw = dir ? t2w : t1w;
        const float* tb = dir ? t2b : t1b;
        const int j = tid;
        float4 w[16];
#pragma unroll
        for (int t = 0; t < 16; t++)
            w[t] = reinterpret_cast<const float4*>(tw + j * 64)[t];
        const float bias = tb[j];
        const int n0 = blockIdx.x * 8;
#pragma unroll 1
        for (int pp = 0; pp < 8; pp++) {
            float a = bias;
            const float4* ap = reinterpret_cast<const float4*>(ms2 + pp * 64);
#pragma unroll
            for (int t = 0; t < 16; t++) {
                float4 v = ap[t];
                a = fmaf(v.x, w[t].x, a);
                a = fmaf(v.y, w[t].y, a);
                a = fmaf(v.z, w[t].z, a);
                a = fmaf(v.w, w[t].w, a);
            }
            out[((size_t)dirb * NPTS + n0 + pp) * OUTCH + j] = a;
        }
    }
}

// ---------------------------------------------------------------------------
extern "C" void kernel_launch(void* const* d_in, const int* in_sizes, int n_in,
                              void* d_out, int out_size) {
    (void)in_sizes; (void)n_in; (void)out_size;
    const float* pc1   = (const float*)d_in[0];
    const float* pc2   = (const float*)d_in[1];
    const float* feat1 = (const float*)d_in[2];
    const float* feat2 = (const float*)d_in[3];
    const float* pos_w = (const float*)d_in[4];
    const float* pos_b = (const float*)d_in[5];
    const float* w0    = (const float*)d_in[6];
    const float* b0    = (const float*)d_in[7];
    const float* w1    = (const float*)d_in[8];
    const float* b1    = (const float*)d_in[9];
    const float* t1w   = (const float*)d_in[10];
    const float* t1b   = (const float*)d_in[11];
    const float* t2w   = (const float*)d_in[12];
    const float* t2b   = (const float*)d_in[13];
    float* out = (float*)d_out;

    pack_kernel<<<(2 * BATCH * NPTS + 255) / 256, 256>>>(pc1, pc2);
    wprep_kernel<<<4, 256>>>(w0, w1);

    // 64KB candidate tile + 4KB ushort slot-major idx = 68KB
    const size_t ksmem = 4 * SEGSZ * sizeof(float) + NSAMPLE * KBT * sizeof(ushort);
    cudaFuncSetAttribute(knn_kernel,
                         cudaFuncAttributeMaxDynamicSharedMemorySize, (int)ksmem);
    dim3 gk(NPTS / KBT, 2 * BATCH);
    knn_kernel<<<gk, KBT, ksmem>>>();

    const size_t smem = (size_t)(8 * HPNT + 192 + 64 * 3) * sizeof(float);
    cudaFuncSetAttribute(feat_kernel,
                         cudaFuncAttributeMaxDynamicSharedMemorySize, (int)smem);
    dim3 gf(NPTS / 8, BATCH, 2);
    feat_kernel<<<gf, 128, smem>>>(feat1, feat2, pos_w, pos_b, b0, b1,
                                   t1w, t1b, t2w, t2b, out);
}

// round 16
// speedup vs baseline: 1.4184x; 1.0041x over previous
#include <cuda_runtime.h>
#include <math_constants.h>
#include <cstdint>

#define NSAMPLE 16
#define NPTS    8192
#define BATCH   2
#define CH      64
#define OUTCH   128
#define SEGSZ   4096              // candidates per tile (2 tiles per kernel)
#define KBT     256               // knn block threads

typedef unsigned long long ull;
typedef unsigned int uint;
typedef unsigned short ushort;

// ---- f32x2 packed helpers (Blackwell) ----
__device__ __forceinline__ ull pk2(float a, float b) {
    ull r; asm("mov.b64 %0,{%1,%2};" : "=l"(r) : "f"(a), "f"(b)); return r;
}
__device__ __forceinline__ void upk2(float& a, float& b, ull r) {
    asm("mov.b64 {%0,%1}, %2;" : "=f"(a), "=f"(b) : "l"(r));
}
__device__ __forceinline__ ull fma2_(ull a, ull b, ull c) {
    ull d; asm("fma.rn.f32x2 %0,%1,%2,%3;" : "=l"(d) : "l"(a), "l"(b), "l"(c)); return d;
}
__device__ __forceinline__ ull mul2_(ull a, ull b) {
    ull d; asm("mul.rn.f32x2 %0,%1,%2;" : "=l"(d) : "l"(a), "l"(b)); return d;
}
__device__ __forceinline__ float leaky(float x) { return x >= 0.0f ? x : 0.1f * x; }
__device__ __forceinline__ uint umax_(uint a, uint b) { return a > b ? a : b; }

#define WSTR 68

// scratch
__device__ float4 g_pts4[2 * BATCH * NPTS];
__device__ int    g_knn[2 * BATCH * NPTS * NSAMPLE];
__device__ float  g_ms[2 * BATCH * NPTS * CH];
__device__ __align__(16) float g_w0T[64 * WSTR];
__device__ __align__(16) float g_w1T[64 * WSTR];

// ---------------------------------------------------------------------------
__global__ void pack_kernel(const float* __restrict__ pc1,
                            const float* __restrict__ pc2) {
    int i = blockIdx.x * blockDim.x + threadIdx.x;
    if (i >= 2 * BATCH * NPTS) return;
    const float* src = (i < BATCH * NPTS) ? pc1 : pc2;
    int r = (i < BATCH * NPTS) ? i : (i - BATCH * NPTS);
    float x = src[r * 3 + 0], y = src[r * 3 + 1], z = src[r * 3 + 2];
    g_pts4[i] = make_float4(x, y, z, x * x + y * y + z * z);
}

__global__ void wprep_kernel(const float* __restrict__ w0,
                             const float* __restrict__ w1) {
    int f = blockIdx.x * blockDim.x + threadIdx.x;   // float4 index, 1024 total
    if (f >= 1024) return;
    float4 a = reinterpret_cast<const float4*>(w0)[f];
    float4 c = reinterpret_cast<const float4*>(w1)[f];
    int o = f >> 4, c0 = (f & 15) * 4;
    g_w0T[(c0 + 0) * WSTR + o] = a.x;
    g_w0T[(c0 + 1) * WSTR + o] = a.y;
    g_w0T[(c0 + 2) * WSTR + o] = a.z;
    g_w0T[(c0 + 3) * WSTR + o] = a.w;
    g_w1T[(c0 + 0) * WSTR + o] = c.x;
    g_w1T[(c0 + 1) * WSTR + o] = c.y;
    g_w1T[(c0 + 2) * WSTR + o] = c.z;
    g_w1T[(c0 + 3) * WSTR + o] = c.w;
}

// ---------------------------------------------------------------------------
// KNN: fused two-tile chained scan. Top-16 keys AND indices live in
// slot-major smem; two halves (slots 0-7 / 8-15) with cached max keys.
// Per hit: 1 STS key + 1 STS idx + rescan of owning half only
// (8 LDS.32 + 7 IMNMX) + cross-max. Key = (dist_bits & ~15) | slot
// (dist clamped >= 0 -> uint order == float order); slot bits MASKED
// when reconstructing the float threshold.
// ---------------------------------------------------------------------------
__global__ void __launch_bounds__(KBT, 2) knn_kernel() {
    extern __shared__ float ks[];
    float*  sx = ks;
    float*  sy = sx + SEGSZ;
    float*  sz = sy + SEGSZ;
    float*  sw = sz + SEGSZ;
    uint*   skey = (uint*)(sw + SEGSZ);          // [16][KBT] 16KB
    ushort* sidx = (ushort*)(skey + 16 * KBT);   // [16][KBT] 8KB

    const int dirb = blockIdx.y;
    const int dir  = dirb >> 1;
    const int b    = dirb & 1;
    const int tid  = threadIdx.x;
    const int n    = blockIdx.x * KBT + tid;
    const size_t q = (size_t)dirb * NPTS + n;

    const float4* Qb = g_pts4 + ((size_t)dir * BATCH + b) * NPTS;
    const float4* Cb0 = g_pts4 + ((size_t)(1 - dir) * BATCH + b) * NPTS;

#pragma unroll
    for (int k = 0; k < NSAMPLE; k++) {
        skey[k * KBT + tid] = 0x7F800000u | (uint)k;
        sidx[k * KBT + tid] = 0;
    }
    uint maxA = 0x7F800007u;     // max key of slots 0-7
    uint maxB = 0x7F80000Fu;     // max key of slots 8-15

    const float4 qv = Qb[n];
    const float sq1 = qv.w;
    const ull qx2 = pk2(qv.x, qv.x);
    const ull qy2 = pk2(qv.y, qv.y);
    const ull qz2 = pk2(qv.z, qv.z);
    const ull m2  = pk2(-2.0f, -2.0f);

    float wds = CUDART_INF_F;

#pragma unroll 1
    for (int pass = 0; pass < 2; pass++) {
        const int base = pass * SEGSZ;
        const float4* Cb = Cb0 + base;

        __syncthreads();   // previous sweep done before tile overwrite
        for (int i = tid; i < SEGSZ; i += KBT) {
            float4 c = Cb[i];
            sx[i] = c.x; sy[i] = c.y; sz[i] = c.z; sw[i] = c.w;
        }
        __syncthreads();

#pragma unroll 1
        for (int j = 0; j < SEGSZ; j += 8) {
            ulonglong2 X0 = *reinterpret_cast<const ulonglong2*>(&sx[j]);
            ulonglong2 X1 = *reinterpret_cast<const ulonglong2*>(&sx[j + 4]);
            ulonglong2 Y0 = *reinterpret_cast<const ulonglong2*>(&sy[j]);
            ulonglong2 Y1 = *reinterpret_cast<const ulonglong2*>(&sy[j + 4]);
            ulonglong2 Z0 = *reinterpret_cast<const ulonglong2*>(&sz[j]);
            ulonglong2 Z1 = *reinterpret_cast<const ulonglong2*>(&sz[j + 4]);
            ulonglong2 W0 = *reinterpret_cast<const ulonglong2*>(&sw[j]);
            ulonglong2 W1 = *reinterpret_cast<const ulonglong2*>(&sw[j + 4]);

            ull t0 = fma2_(qx2, X0.x, fma2_(qy2, Y0.x, mul2_(qz2, Z0.x)));
            ull t1 = fma2_(qx2, X0.y, fma2_(qy2, Y0.y, mul2_(qz2, Z0.y)));
            ull t2 = fma2_(qx2, X1.x, fma2_(qy2, Y1.x, mul2_(qz2, Z1.x)));
            ull t3 = fma2_(qx2, X1.y, fma2_(qy2, Y1.y, mul2_(qz2, Z1.y)));
            ull s01 = fma2_(m2, t0, W0.x);
            ull s23 = fma2_(m2, t1, W0.y);
            ull s45 = fma2_(m2, t2, W1.x);
            ull s67 = fma2_(m2, t3, W1.y);

            float s[8];
            upk2(s[0], s[1], s01);
            upk2(s[2], s[3], s23);
            upk2(s[4], s[5], s45);
            upk2(s[6], s[7], s67);

            float m4a = fminf(fminf(s[0], s[1]), fminf(s[2], s[3]));
            float m4b = fminf(fminf(s[4], s[5]), fminf(s[6], s[7]));
            float m8  = fminf(m4a, m4b);

            if (m8 < wds) {
#pragma unroll
                for (int g = 0; g < 2; g++) {
                    float mg = g ? m4b : m4a;
                    if (mg < wds) {
#pragma unroll
                        for (int t = 0; t < 4; t++) {
                            float sv = s[g * 4 + t];
                            if (sv < wds) {
                                float d = sv + sq1;
                                uint wdkey = umax_(maxA, maxB);
                                uint slot = wdkey & 15u;
                                uint nk = (__float_as_uint(fmaxf(d, 0.0f)) & 0xFFFFFFF0u) | slot;
                                skey[slot * KBT + tid] = nk;
                                sidx[slot * KBT + tid] = (ushort)(base + j + g * 4 + t);
                                if (maxA > maxB) {
                                    // rescan half A (slots 0-7)
                                    uint u0 = skey[0 * KBT + tid];
                                    uint u1 = skey[1 * KBT + tid];
                                    uint u2 = skey[2 * KBT + tid];
                                    uint u3 = skey[3 * KBT + tid];
                                    uint u4 = skey[4 * KBT + tid];
                                    uint u5 = skey[5 * KBT + tid];
                                    uint u6 = skey[6 * KBT + tid];
                                    uint u7 = skey[7 * KBT + tid];
                                    maxA = umax_(umax_(umax_(u0, u1), umax_(u2, u3)),
                                                 umax_(umax_(u4, u5), umax_(u6, u7)));
                                } else {
                                    // rescan half B (slots 8-15)
                                    uint u0 = skey[8  * KBT + tid];
                                    uint u1 = skey[9  * KBT + tid];
                                    uint u2 = skey[10 * KBT + tid];
                                    uint u3 = skey[11 * KBT + tid];
                                    uint u4 = skey[12 * KBT + tid];
                                    uint u5 = skey[13 * KBT + tid];
                                    uint u6 = skey[14 * KBT + tid];
                                    uint u7 = skey[15 * KBT + tid];
                                    maxB = umax_(umax_(umax_(u0, u1), umax_(u2, u3)),
                                                 umax_(umax_(u4, u5), umax_(u6, u7)));
                                }
                                wds = __uint_as_float(umax_(maxA, maxB) & 0xFFFFFFF0u) - sq1;
                            }
                        }
                    }
                }
            }
        }
    }

    // slot k's key always carries slot id k -> indices are already slot-ordered
    int* outp = g_knn + q * NSAMPLE;
#pragma unroll
    for (int k = 0; k < NSAMPLE; k++)
        outp[k] = (int)sidx[k * KBT + tid];
}

// ---------------------------------------------------------------------------
// feat (R13 known-good): 128 threads = 8 points x 16 threads; k8 x o8 f32x2
// tiles; weights from pre-transposed global (L1); pm aliases hs.
// ---------------------------------------------------------------------------
#define HROWS 68
#define HPNT  1128

__device__ __forceinline__ int hoff(int p, int k) {
    return p * HPNT + k * HROWS + ((k >> 3) << 4);
}

__global__ void __launch_bounds__(128, 4) feat_kernel(
        const float* __restrict__ feat1,
        const float* __restrict__ feat2,
        const float* __restrict__ pos_w,
        const float* __restrict__ pos_b,
        const float* __restrict__ b0,
        const float* __restrict__ b1) {
    extern __shared__ float sm[];
    float* hs    = sm;                         // 9024
    float* pm    = hs;                         // ALIAS: hs dead after layer 2
    float* posws = hs + 8 * HPNT;              // 192
    float* posbs = posws + 192;                // 64
    float* b0s   = posbs + 64;                 // 64
    float* b1s   = b0s + 64;                   // 64

    const int dir = blockIdx.z;
    const int b   = blockIdx.y;
    const int tid = threadIdx.x;
    const int dirb = dir * BATCH + b;

    if (tid < 64) {
        posbs[tid] = pos_b[tid];
        b0s[tid]   = b0[tid];
        b1s[tid]   = b1[tid];
    }
    for (int i = tid; i < 192; i += 128) posws[i] = pos_w[i];
    __syncthreads();

    const float* F1 = dir ? feat2 : feat1;
    const float* F2 = dir ? feat1 : feat2;
    const float4* QC = g_pts4 + ((size_t)dir * BATCH + b) * NPTS;
    const float4* NC = g_pts4 + ((size_t)(1 - dir) * BATCH + b) * NPTS;

    // ---- stage 1: gather + pos feat + leaky -> hs ----
    {
        const int c  = tid & 63;
        const int rh = tid >> 6;
        const float pwx = posws[c * 3 + 0];
        const float pwy = posws[c * 3 + 1];
        const float pwz = posws[c * 3 + 2];
        const float pb  = posbs[c];
        for (int it = 0; it < 64; it++) {
            int row = it * 2 + rh;
            int p = row >> 4, k = row & 15;
            int n = blockIdx.x * 8 + p;
            int id = g_knn[((size_t)dirb * NPTS + n) * NSAMPLE + k];
            float4 cc = NC[id];
            float4 qq = QC[n];
            float g   = F2[((size_t)b * NPTS + id) * CH + c];
            float p1o = F1[((size_t)b * NPTS + n) * CH + c];
            float h = g + p1o +
                fmaf(pwx, cc.x - qq.x, fmaf(pwy, cc.y - qq.y,
                fmaf(pwz, cc.z - qq.z, pb)));
            hs[hoff(p, k) + c] = leaky(h);
        }
    }
    __syncthreads();

    const int tt = tid & 15;
    const int p  = tid >> 4;
    const int o0 = (tt & 7) * 8;
    const int k0 = (tt >> 3) * 8;
    float* hp2 = hs + hoff(p, k0);

    ull acc[8][4];

    // =============== layer 1 ===============
    {
        ulonglong2 bA = *reinterpret_cast<const ulonglong2*>(b0s + o0);
        ulonglong2 bB = *reinterpret_cast<const ulonglong2*>(b0s + o0 + 4);
#pragma unroll
        for (int ki = 0; ki < 8; ki++) {
            acc[ki][0] = bA.x; acc[ki][1] = bA.y;
            acc[ki][2] = bB.x; acc[ki][3] = bB.y;
        }
#pragma unroll 1
        for (int c = 0; c < 64; c += 4) {
            const float* wp = g_w0T + c * WSTR + o0;
            ulonglong2 wa0 = *reinterpret_cast<const ulonglong2*>(wp);
            ulonglong2 wa1 = *reinterpret_cast<const ulonglong2*>(wp + 4);
            ulonglong2 wb0 = *reinterpret_cast<const ulonglong2*>(wp + WSTR);
            ulonglong2 wb1 = *reinterpret_cast<const ulonglong2*>(wp + WSTR + 4);
            ulonglong2 wc0 = *reinterpret_cast<const ulonglong2*>(wp + 2 * WSTR);
            ulonglong2 wc1 = *reinterpret_cast<const ulonglong2*>(wp + 2 * WSTR + 4);
            ulonglong2 wd0 = *reinterpret_cast<const ulonglong2*>(wp + 3 * WSTR);
            ulonglong2 wd1 = *reinterpret_cast<const ulonglong2*>(wp + 3 * WSTR + 4);
#pragma unroll
            for (int ki = 0; ki < 8; ki++) {
                float4 hv = *reinterpret_cast<const float4*>(hp2 + ki * HROWS + c);
                ull h0 = pk2(hv.x, hv.x);
                ull h1 = pk2(hv.y, hv.y);
                ull h2 = pk2(hv.z, hv.z);
                ull h3 = pk2(hv.w, hv.w);
                acc[ki][0] = fma2_(h0, wa0.x, acc[ki][0]);
                acc[ki][1] = fma2_(h0, wa0.y, acc[ki][1]);
                acc[ki][2] = fma2_(h0, wa1.x, acc[ki][2]);
                acc[ki][3] = fma2_(h0, wa1.y, acc[ki][3]);
                acc[ki][0] = fma2_(h1, wb0.x, acc[ki][0]);
                acc[ki][1] = fma2_(h1, wb0.y, acc[ki][1]);
                acc[ki][2] = fma2_(h1, wb1.x, acc[ki][2]);
                acc[ki][3] = fma2_(h1, wb1.y, acc[ki][3]);
                acc[ki][0] = fma2_(h2, wc0.x, acc[ki][0]);
                acc[ki][1] = fma2_(h2, wc0.y, acc[ki][1]);
                acc[ki][2] = fma2_(h2, wc1.x, acc[ki][2]);
                acc[ki][3] = fma2_(h2, wc1.y, acc[ki][3]);
                acc[ki][0] = fma2_(h3, wd0.x, acc[ki][0]);
                acc[ki][1] = fma2_(h3, wd0.y, acc[ki][1]);
                acc[ki][2] = fma2_(h3, wd1.x, acc[ki][2]);
                acc[ki][3] = fma2_(h3, wd1.y, acc[ki][3]);
            }
        }
    }
    __syncthreads();
#pragma unroll
    for (int ki = 0; ki < 8; ki++) {
        float a0, a1, a2, a3, a4, a5, a6, a7;
        upk2(a0, a1, acc[ki][0]);
        upk2(a2, a3, acc[ki][1]);
        upk2(a4, a5, acc[ki][2]);
        upk2(a6, a7, acc[ki][3]);
        float4 v0 = make_float4(leaky(a0), leaky(a1), leaky(a2), leaky(a3));
        float4 v1 = make_float4(leaky(a4), leaky(a5), leaky(a6), leaky(a7));
        *reinterpret_cast<float4*>(hp2 + ki * HROWS + o0)     = v0;
        *reinterpret_cast<float4*>(hp2 + ki * HROWS + o0 + 4) = v1;
    }
    __syncthreads();

    // =============== layer 2 ===============
    {
        ulonglong2 bA = *reinterpret_cast<const ulonglong2*>(b1s + o0);
        ulonglong2 bB = *reinterpret_cast<const ulonglong2*>(b1s + o0 + 4);
#pragma unroll
        for (int ki = 0; ki < 8; ki++) {
            acc[ki][0] = bA.x; acc[ki][1] = bA.y;
            acc[ki][2] = bB.x; acc[ki][3] = bB.y;
        }
#pragma unroll 1
        for (int c = 0; c < 64; c += 4) {
            const float* wp = g_w1T + c * WSTR + o0;
            ulonglong2 wa0 = *reinterpret_cast<const ulonglong2*>(wp);
            ulonglong2 wa1 = *reinterpret_cast<const ulonglong2*>(wp + 4);
            ulonglong2 wb0 = *reinterpret_cast<const ulonglong2*>(wp + WSTR);
            ulonglong2 wb1 = *reinterpret_cast<const ulonglong2*>(wp + WSTR + 4);
            ulonglong2 wc0 = *reinterpret_cast<const ulonglong2*>(wp + 2 * WSTR);
            ulonglong2 wc1 = *reinterpret_cast<const ulonglong2*>(wp + 2 * WSTR + 4);
            ulonglong2 wd0 = *reinterpret_cast<const ulonglong2*>(wp + 3 * WSTR);
            ulonglong2 wd1 = *reinterpret_cast<const ulonglong2*>(wp + 3 * WSTR + 4);
#pragma unroll
            for (int ki = 0; ki < 8; ki++) {
                float4 hv = *reinterpret_cast<const float4*>(hp2 + ki * HROWS + c);
                ull h0 = pk2(hv.x, hv.x);
                ull h1 = pk2(hv.y, hv.y);
                ull h2 = pk2(hv.z, hv.z);
                ull h3 = pk2(hv.w, hv.w);
                acc[ki][0] = fma2_(h0, wa0.x, acc[ki][0]);
                acc[ki][1] = fma2_(h0, wa0.y, acc[ki][1]);
                acc[ki][2] = fma2_(h0, wa1.x, acc[ki][2]);
                acc[ki][3] = fma2_(h0, wa1.y, acc[ki][3]);
                acc[ki][0] = fma2_(h1, wb0.x, acc[ki][0]);
                acc[ki][1] = fma2_(h1, wb0.y, acc[ki][1]);
                acc[ki][2] = fma2_(h1, wb1.x, acc[ki][2]);
                acc[ki][3] = fma2_(h1, wb1.y, acc[ki][3]);
                acc[ki][0] = fma2_(h2, wc0.x, acc[ki][0]);
                acc[ki][1] = fma2_(h2, wc0.y, acc[ki][1]);
                acc[ki][2] = fma2_(h2, wc1.x, acc[ki][2]);
                acc[ki][3] = fma2_(h2, wc1.y, acc[ki][3]);
                acc[ki][0] = fma2_(h3, wd0.x, acc[ki][0]);
                acc[ki][1] = fma2_(h3, wd0.y, acc[ki][1]);
                acc[ki][2] = fma2_(h3, wd1.x, acc[ki][2]);
                acc[ki][3] = fma2_(h3, wd1.y, acc[ki][3]);
            }
        }
    }

    __syncthreads();   // hs dead; pm aliases it

    {
        float mx[8];
#pragma unroll
        for (int j = 0; j < 8; j++) mx[j] = -CUDART_INF_F;
#pragma unroll
        for (int ki = 0; ki < 8; ki++) {
            float a0, a1, a2, a3, a4, a5, a6, a7;
            upk2(a0, a1, acc[ki][0]);
            upk2(a2, a3, acc[ki][1]);
            upk2(a4, a5, acc[ki][2]);
            upk2(a6, a7, acc[ki][3]);
            mx[0] = fmaxf(mx[0], leaky(a0));
            mx[1] = fmaxf(mx[1], leaky(a1));
            mx[2] = fmaxf(mx[2], leaky(a2));
            mx[3] = fmaxf(mx[3], leaky(a3));
            mx[4] = fmaxf(mx[4], leaky(a4));
            mx[5] = fmaxf(mx[5], leaky(a5));
            mx[6] = fmaxf(mx[6], leaky(a6));
            mx[7] = fmaxf(mx[7], leaky(a7));
        }
        float* pmp = pm + p * 128 + (k0 >> 3) * 64 + o0;
        *reinterpret_cast<float4*>(pmp)     = make_float4(mx[0], mx[1], mx[2], mx[3]);
        *reinterpret_cast<float4*>(pmp + 4) = make_float4(mx[4], mx[5], mx[6], mx[7]);
    }
    __syncthreads();

#pragma unroll
    for (int i = 0; i < 4; i++) {
        int ii = tid + i * 128;
        int pp = ii >> 6, oo = ii & 63;
        float mm = fmaxf(pm[pp * 128 + oo], pm[pp * 128 + 64 + oo]);
        int nn = blockIdx.x * 8 + pp;
        g_ms[((size_t)dirb * NPTS + nn) * CH + oo] = mm;
    }
}

// ---------------------------------------------------------------------------
// proj (R13): 128 threads = 128 output channels; weight row in registers,
// 64 points staged in smem, broadcast LDS.128 activations.
// ---------------------------------------------------------------------------
#define PPROJ 64
__global__ void __launch_bounds__(128) proj_kernel(
        const float* __restrict__ t1w, const float* __restrict__ t1b,
        const float* __restrict__ t2w, const float* __restrict__ t2b,
        float* __restrict__ out) {
    __shared__ float aS[PPROJ * 64];

    const int dir = blockIdx.z;
    const int b   = blockIdx.y;
    const int j   = threadIdx.x;
    const int dirb = dir * BATCH + b;

    const float* tw = dir ? t2w : t1w;
    const float* tb = dir ? t2b : t1b;

    float4 w[16];
#pragma unroll
    for (int t = 0; t < 16; t++)
        w[t] = reinterpret_cast<const float4*>(tw + j * 64)[t];
    const float bias = tb[j];

    const int n0 = blockIdx.x * PPROJ;
#pragma unroll
    for (int i = 0; i < PPROJ * 64 / 128 / 4; i++) {
        int f = j + i * 128;
        reinterpret_cast<float4*>(aS)[f] =
            reinterpret_cast<const float4*>(g_ms + ((size_t)dirb * NPTS + n0) * CH)[f];
    }
    __syncthreads();

#pragma unroll 2
    for (int p = 0; p < PPROJ; p++) {
        float acc = bias;
        const float4* ap = reinterpret_cast<const float4*>(aS + p * 64);
#pragma unroll
        for (int t = 0; t < 16; t++) {
            float4 a = ap[t];
            acc = fmaf(a.x, w[t].x, acc);
            acc = fmaf(a.y, w[t].y, acc);
            acc = fmaf(a.z, w[t].z, acc);
            acc = fmaf(a.w, w[t].w, acc);
        }
        out[((size_t)dirb * NPTS + n0 + p) * OUTCH + j] = acc;
    }
}

// ---------------------------------------------------------------------------
extern "C" void kernel_launch(void* const* d_in, const int* in_sizes, int n_in,
                              void* d_out, int out_size) {
    (void)in_sizes; (void)n_in; (void)out_size;
    const float* pc1   = (const float*)d_in[0];
    const float* pc2   = (const float*)d_in[1];
    const float* feat1 = (const float*)d_in[2];
    const float* feat2 = (const float*)d_in[3];
    const float* pos_w = (const float*)d_in[4];
    const float* pos_b = (const float*)d_in[5];
    const float* w0    = (const float*)d_in[6];
    const float* b0    = (const float*)d_in[7];
    const float* w1    = (const float*)d_in[8];
    const float* b1    = (const float*)d_in[9];
    const float* t1w   = (const float*)d_in[10];
    const float* t1b   = (const float*)d_in[11];
    const float* t2w   = (const float*)d_in[12];
    const float* t2b   = (const float*)d_in[13];
    float* out = (float*)d_out;

    pack_kernel<<<(2 * BATCH * NPTS + 255) / 256, 256>>>(pc1, pc2);
    wprep_kernel<<<4, 256>>>(w0, w1);

    // 64KB tile + 16KB keys + 8KB idx = 88KB
    const size_t ksmem = 4 * SEGSZ * sizeof(float)
                       + NSAMPLE * KBT * sizeof(uint)
                       + NSAMPLE * KBT * sizeof(ushort);
    cudaFuncSetAttribute(knn_kernel,
                         cudaFuncAttributeMaxDynamicSharedMemorySize, (int)ksmem);
    dim3 gk(NPTS / KBT, 2 * BATCH);
    knn_kernel<<<gk, KBT, ksmem>>>();

    const size_t smem = (size_t)(8 * HPNT + 192 + 64 * 3) * sizeof(float);
    cudaFuncSetAttribute(feat_kernel,
                         cudaFuncAttributeMaxDynamicSharedMemorySize, (int)smem);
    dim3 gf(NPTS / 8, BATCH, 2);
    feat_kernel<<<gf, 128, smem>>>(feat1, feat2, pos_w, pos_b, b0, b1);

    dim3 gp(NPTS / PPROJ, BATCH, 2);
    proj_kernel<<<gp, 128>>>(t1w, t1b, t2w, t2b, out);
}

// round 17
// speedup vs baseline: 1.6165x; 1.1397x over previous
#include <cuda_runtime.h>
#include <math_constants.h>
#include <cstdint>

#define NSAMPLE 16
#define NPTS    8192
#define BATCH   2
#define CH      64
#define OUTCH   128
#define SEGSZ   4096              // candidates per tile (2 tiles per kernel)
#define KBT     256               // knn block threads

typedef unsigned long long ull;
typedef unsigned int uint;
typedef unsigned short ushort;

// ---- f32x2 packed helpers (Blackwell) ----
__device__ __forceinline__ ull pk2(float a, float b) {
    ull r; asm("mov.b64 %0,{%1,%2};" : "=l"(r) : "f"(a), "f"(b)); return r;
}
__device__ __forceinline__ void upk2(float& a, float& b, ull r) {
    asm("mov.b64 {%0,%1}, %2;" : "=f"(a), "=f"(b) : "l"(r));
}
__device__ __forceinline__ ull fma2_(ull a, ull b, ull c) {
    ull d; asm("fma.rn.f32x2 %0,%1,%2,%3;" : "=l"(d) : "l"(a), "l"(b), "l"(c)); return d;
}
__device__ __forceinline__ ull mul2_(ull a, ull b) {
    ull d; asm("mul.rn.f32x2 %0,%1,%2;" : "=l"(d) : "l"(a), "l"(b)); return d;
}
__device__ __forceinline__ float leaky(float x) { return x >= 0.0f ? x : 0.1f * x; }
__device__ __forceinline__ uint umax_(uint a, uint b) { return a > b ? a : b; }

#define WSTR 68

// scratch
__device__ float4 g_pts4[2 * BATCH * NPTS];
__device__ int    g_knn[2 * BATCH * NPTS * NSAMPLE];
__device__ float  g_ms[2 * BATCH * NPTS * CH];
__device__ __align__(16) float g_w0T[64 * WSTR];
__device__ __align__(16) float g_w1T[64 * WSTR];

// ---------------------------------------------------------------------------
__global__ void pack_kernel(const float* __restrict__ pc1,
                            const float* __restrict__ pc2) {
    int i = blockIdx.x * blockDim.x + threadIdx.x;
    if (i >= 2 * BATCH * NPTS) return;
    const float* src = (i < BATCH * NPTS) ? pc1 : pc2;
    int r = (i < BATCH * NPTS) ? i : (i - BATCH * NPTS);
    float x = src[r * 3 + 0], y = src[r * 3 + 1], z = src[r * 3 + 2];
    g_pts4[i] = make_float4(x, y, z, x * x + y * y + z * z);
}

__global__ void wprep_kernel(const float* __restrict__ w0,
                             const float* __restrict__ w1) {
    int f = blockIdx.x * blockDim.x + threadIdx.x;   // float4 index, 1024 total
    if (f >= 1024) return;
    float4 a = reinterpret_cast<const float4*>(w0)[f];
    float4 c = reinterpret_cast<const float4*>(w1)[f];
    int o = f >> 4, c0 = (f & 15) * 4;
    g_w0T[(c0 + 0) * WSTR + o] = a.x;
    g_w0T[(c0 + 1) * WSTR + o] = a.y;
    g_w0T[(c0 + 2) * WSTR + o] = a.z;
    g_w0T[(c0 + 3) * WSTR + o] = a.w;
    g_w1T[(c0 + 0) * WSTR + o] = c.x;
    g_w1T[(c0 + 1) * WSTR + o] = c.y;
    g_w1T[(c0 + 2) * WSTR + o] = c.z;
    g_w1T[(c0 + 3) * WSTR + o] = c.w;
}

// ---------------------------------------------------------------------------
// KNN: fused two-tile chained scan (R13 state layout: register keys,
// slot-major ushort idx smem). Hit path flattened: ONE guard branch per
// 8-candidate batch, then a branchless value-ordered extract loop
// (argmin-8 with index tracking -> single insert -> invalidate -> re-min).
// Replace-max set semantics are insertion-order invariant, so the final
// top-16 set is identical to the R13 index-ordered version.
// ---------------------------------------------------------------------------
__global__ void __launch_bounds__(KBT, 3) knn_kernel() {
    extern __shared__ float ks[];
    float*  sx = ks;
    float*  sy = sx + SEGSZ;
    float*  sz = sy + SEGSZ;
    float*  sw = sz + SEGSZ;
    ushort* sidx = (ushort*)(sw + SEGSZ);    // [16][KBT], GLOBAL candidate idx

    const int dirb = blockIdx.y;
    const int dir  = dirb >> 1;
    const int b    = dirb & 1;
    const int tid  = threadIdx.x;
    const int n    = blockIdx.x * KBT + tid;
    const size_t q = (size_t)dirb * NPTS + n;

    const float4* Qb = g_pts4 + ((size_t)dir * BATCH + b) * NPTS;
    const float4* Cb0 = g_pts4 + ((size_t)(1 - dir) * BATCH + b) * NPTS;

    uint bk[NSAMPLE];
#pragma unroll
    for (int k = 0; k < NSAMPLE; k++) {
        bk[k] = 0x7F800000u | k;
        sidx[k * KBT + tid] = 0;
    }
    uint wdkey = 0x7F80000Fu;

    const float4 qv = Qb[n];
    const float sq1 = qv.w;
    const ull qx2 = pk2(qv.x, qv.x);
    const ull qy2 = pk2(qv.y, qv.y);
    const ull qz2 = pk2(qv.z, qv.z);
    const ull m2  = pk2(-2.0f, -2.0f);

    float wds = CUDART_INF_F;

#pragma unroll 1
    for (int pass = 0; pass < 2; pass++) {
        const int base = pass * SEGSZ;
        const float4* Cb = Cb0 + base;

        __syncthreads();   // previous sweep done before tile overwrite
        for (int i = tid; i < SEGSZ; i += KBT) {
            float4 c = Cb[i];
            sx[i] = c.x; sy[i] = c.y; sz[i] = c.z; sw[i] = c.w;
        }
        __syncthreads();

#pragma unroll 1
        for (int j = 0; j < SEGSZ; j += 8) {
            ulonglong2 X0 = *reinterpret_cast<const ulonglong2*>(&sx[j]);
            ulonglong2 X1 = *reinterpret_cast<const ulonglong2*>(&sx[j + 4]);
            ulonglong2 Y0 = *reinterpret_cast<const ulonglong2*>(&sy[j]);
            ulonglong2 Y1 = *reinterpret_cast<const ulonglong2*>(&sy[j + 4]);
            ulonglong2 Z0 = *reinterpret_cast<const ulonglong2*>(&sz[j]);
            ulonglong2 Z1 = *reinterpret_cast<const ulonglong2*>(&sz[j + 4]);
            ulonglong2 W0 = *reinterpret_cast<const ulonglong2*>(&sw[j]);
            ulonglong2 W1 = *reinterpret_cast<const ulonglong2*>(&sw[j + 4]);

            ull t0 = fma2_(qx2, X0.x, fma2_(qy2, Y0.x, mul2_(qz2, Z0.x)));
            ull t1 = fma2_(qx2, X0.y, fma2_(qy2, Y0.y, mul2_(qz2, Z0.y)));
            ull t2 = fma2_(qx2, X1.x, fma2_(qy2, Y1.x, mul2_(qz2, Z1.x)));
            ull t3 = fma2_(qx2, X1.y, fma2_(qy2, Y1.y, mul2_(qz2, Z1.y)));
            ull s01 = fma2_(m2, t0, W0.x);
            ull s23 = fma2_(m2, t1, W0.y);
            ull s45 = fma2_(m2, t2, W1.x);
            ull s67 = fma2_(m2, t3, W1.y);

            float s[8];
            upk2(s[0], s[1], s01);
            upk2(s[2], s[3], s23);
            upk2(s[4], s[5], s45);
            upk2(s[6], s[7], s67);

            float m8 = fminf(fminf(fminf(s[0], s[1]), fminf(s[2], s[3])),
                             fminf(fminf(s[4], s[5]), fminf(s[6], s[7])));

            if (m8 < wds) {
                // value-ordered extract loop (branchless body)
                do {
                    // argmin of s[0..7] with index tracking (predicated tree)
                    float v0 = fminf(s[0], s[1]); int p0 = (s[1] < s[0]) ? 1 : 0;
                    float v1 = fminf(s[2], s[3]); int p1 = (s[3] < s[2]) ? 3 : 2;
                    float v2 = fminf(s[4], s[5]); int p2 = (s[5] < s[4]) ? 5 : 4;
                    float v3 = fminf(s[6], s[7]); int p3 = (s[7] < s[6]) ? 7 : 6;
                    float u0 = fminf(v0, v1);     int q0 = (v1 < v0) ? p1 : p0;
                    float u1 = fminf(v2, v3);     int q1 = (v3 < v2) ? p3 : p2;
                    float mv = fminf(u0, u1);
                    int   mp = (u1 < u0) ? q1 : q0;

                    // insert (R13 semantics)
                    float d = mv + sq1;
                    uint slot = wdkey & 15u;
                    uint nk = (__float_as_uint(fmaxf(d, 0.0f)) & 0xFFFFFFF0u) | slot;
                    sidx[slot * KBT + tid] = (ushort)(base + j + mp);
#pragma unroll
                    for (int k = 0; k < NSAMPLE; k++)
                        bk[k] = (bk[k] == wdkey) ? nk : bk[k];
                    uint m0[8];
#pragma unroll
                    for (int k = 0; k < 8; k++) m0[k] = umax_(bk[2*k], bk[2*k+1]);
                    uint m1[4];
#pragma unroll
                    for (int k = 0; k < 4; k++) m1[k] = umax_(m0[2*k], m0[2*k+1]);
                    wdkey = umax_(umax_(m1[0], m1[1]), umax_(m1[2], m1[3]));
                    wds = __uint_as_float(wdkey & 0xFFFFFFF0u) - sq1;

                    // invalidate inserted lane (predicated) + re-min
#pragma unroll
                    for (int t = 0; t < 8; t++)
                        s[t] = (t == mp) ? CUDART_INF_F : s[t];
                    m8 = fminf(fminf(fminf(s[0], s[1]), fminf(s[2], s[3])),
                               fminf(fminf(s[4], s[5]), fminf(s[6], s[7])));
                } while (m8 < wds);
            }
        }
    }

    int* outp = g_knn + q * NSAMPLE;
#pragma unroll
    for (int k = 0; k < NSAMPLE; k++)
        outp[k] = (int)sidx[(bk[k] & 15u) * KBT + tid];
}

// ---------------------------------------------------------------------------
// feat (R13 known-good): 128 threads = 8 points x 16 threads; k8 x o8 f32x2
// tiles; weights from pre-transposed global (L1); pm aliases hs.
// ---------------------------------------------------------------------------
#define HROWS 68
#define HPNT  1128

__device__ __forceinline__ int hoff(int p, int k) {
    return p * HPNT + k * HROWS + ((k >> 3) << 4);
}

__global__ void __launch_bounds__(128, 4) feat_kernel(
        const float* __restrict__ feat1,
        const float* __restrict__ feat2,
        const float* __restrict__ pos_w,
        const float* __restrict__ pos_b,
        const float* __restrict__ b0,
        const float* __restrict__ b1) {
    extern __shared__ float sm[];
    float* hs    = sm;                         // 9024
    float* pm    = hs;                         // ALIAS: hs dead after layer 2
    float* posws = hs + 8 * HPNT;              // 192
    float* posbs = posws + 192;                // 64
    float* b0s   = posbs + 64;                 // 64
    float* b1s   = b0s + 64;                   // 64

    const int dir = blockIdx.z;
    const int b   = blockIdx.y;
    const int tid = threadIdx.x;
    const int dirb = dir * BATCH + b;

    if (tid < 64) {
        posbs[tid] = pos_b[tid];
        b0s[tid]   = b0[tid];
        b1s[tid]   = b1[tid];
    }
    for (int i = tid; i < 192; i += 128) posws[i] = pos_w[i];
    __syncthreads();

    const float* F1 = dir ? feat2 : feat1;
    const float* F2 = dir ? feat1 : feat2;
    const float4* QC = g_pts4 + ((size_t)dir * BATCH + b) * NPTS;
    const float4* NC = g_pts4 + ((size_t)(1 - dir) * BATCH + b) * NPTS;

    // ---- stage 1: gather + pos feat + leaky -> hs ----
    {
        const int c  = tid & 63;
        const int rh = tid >> 6;
        const float pwx = posws[c * 3 + 0];
        const float pwy = posws[c * 3 + 1];
        const float pwz = posws[c * 3 + 2];
        const float pb  = posbs[c];
        for (int it = 0; it < 64; it++) {
            int row = it * 2 + rh;
            int p = row >> 4, k = row & 15;
            int n = blockIdx.x * 8 + p;
            int id = g_knn[((size_t)dirb * NPTS + n) * NSAMPLE + k];
            float4 cc = NC[id];
            float4 qq = QC[n];
            float g   = F2[((size_t)b * NPTS + id) * CH + c];
            float p1o = F1[((size_t)b * NPTS + n) * CH + c];
            float h = g + p1o +
                fmaf(pwx, cc.x - qq.x, fmaf(pwy, cc.y - qq.y,
                fmaf(pwz, cc.z - qq.z, pb)));
            hs[hoff(p, k) + c] = leaky(h);
        }
    }
    __syncthreads();

    const int tt = tid & 15;
    const int p  = tid >> 4;
    const int o0 = (tt & 7) * 8;
    const int k0 = (tt >> 3) * 8;
    float* hp2 = hs + hoff(p, k0);

    ull acc[8][4];

    // =============== layer 1 ===============
    {
        ulonglong2 bA = *reinterpret_cast<const ulonglong2*>(b0s + o0);
        ulonglong2 bB = *reinterpret_cast<const ulonglong2*>(b0s + o0 + 4);
#pragma unroll
        for (int ki = 0; ki < 8; ki++) {
            acc[ki][0] = bA.x; acc[ki][1] = bA.y;
            acc[ki][2] = bB.x; acc[ki][3] = bB.y;
        }
#pragma unroll 1
        for (int c = 0; c < 64; c += 4) {
            const float* wp = g_w0T + c * WSTR + o0;
            ulonglong2 wa0 = *reinterpret_cast<const ulonglong2*>(wp);
            ulonglong2 wa1 = *reinterpret_cast<const ulonglong2*>(wp + 4);
            ulonglong2 wb0 = *reinterpret_cast<const ulonglong2*>(wp + WSTR);
            ulonglong2 wb1 = *reinterpret_cast<const ulonglong2*>(wp + WSTR + 4);
            ulonglong2 wc0 = *reinterpret_cast<const ulonglong2*>(wp + 2 * WSTR);
            ulonglong2 wc1 = *reinterpret_cast<const ulonglong2*>(wp + 2 * WSTR + 4);
            ulonglong2 wd0 = *reinterpret_cast<const ulonglong2*>(wp + 3 * WSTR);
            ulonglong2 wd1 = *reinterpret_cast<const ulonglong2*>(wp + 3 * WSTR + 4);
#pragma unroll
            for (int ki = 0; ki < 8; ki++) {
                float4 hv = *reinterpret_cast<const float4*>(hp2 + ki * HROWS + c);
                ull h0 = pk2(hv.x, hv.x);
                ull h1 = pk2(hv.y, hv.y);
                ull h2 = pk2(hv.z, hv.z);
                ull h3 = pk2(hv.w, hv.w);
                acc[ki][0] = fma2_(h0, wa0.x, acc[ki][0]);
                acc[ki][1] = fma2_(h0, wa0.y, acc[ki][1]);
                acc[ki][2] = fma2_(h0, wa1.x, acc[ki][2]);
                acc[ki][3] = fma2_(h0, wa1.y, acc[ki][3]);
                acc[ki][0] = fma2_(h1, wb0.x, acc[ki][0]);
                acc[ki][1] = fma2_(h1, wb0.y, acc[ki][1]);
                acc[ki][2] = fma2_(h1, wb1.x, acc[ki][2]);
                acc[ki][3] = fma2_(h1, wb1.y, acc[ki][3]);
                acc[ki][0] = fma2_(h2, wc0.x, acc[ki][0]);
                acc[ki][1] = fma2_(h2, wc0.y, acc[ki][1]);
                acc[ki][2] = fma2_(h2, wc1.x, acc[ki][2]);
                acc[ki][3] = fma2_(h2, wc1.y, acc[ki][3]);
                acc[ki][0] = fma2_(h3, wd0.x, acc[ki][0]);
                acc[ki][1] = fma2_(h3, wd0.y, acc[ki][1]);
                acc[ki][2] = fma2_(h3, wd1.x, acc[ki][2]);
                acc[ki][3] = fma2_(h3, wd1.y, acc[ki][3]);
            }
        }
    }
    __syncthreads();
#pragma unroll
    for (int ki = 0; ki < 8; ki++) {
        float a0, a1, a2, a3, a4, a5, a6, a7;
        upk2(a0, a1, acc[ki][0]);
        upk2(a2, a3, acc[ki][1]);
        upk2(a4, a5, acc[ki][2]);
        upk2(a6, a7, acc[ki][3]);
        float4 v0 = make_float4(leaky(a0), leaky(a1), leaky(a2), leaky(a3));
        float4 v1 = make_float4(leaky(a4), leaky(a5), leaky(a6), leaky(a7));
        *reinterpret_cast<float4*>(hp2 + ki * HROWS + o0)     = v0;
        *reinterpret_cast<float4*>(hp2 + ki * HROWS + o0 + 4) = v1;
    }
    __syncthreads();

    // =============== layer 2 ===============
    {
        ulonglong2 bA = *reinterpret_cast<const ulonglong2*>(b1s + o0);
        ulonglong2 bB = *reinterpret_cast<const ulonglong2*>(b1s + o0 + 4);
#pragma unroll
        for (int ki = 0; ki < 8; ki++) {
            acc[ki][0] = bA.x; acc[ki][1] = bA.y;
            acc[ki][2] = bB.x; acc[ki][3] = bB.y;
        }
#pragma unroll 1
        for (int c = 0; c < 64; c += 4) {
            const float* wp = g_w1T + c * WSTR + o0;
            ulonglong2 wa0 = *reinterpret_cast<const ulonglong2*>(wp);
            ulonglong2 wa1 = *reinterpret_cast<const ulonglong2*>(wp + 4);
            ulonglong2 wb0 = *reinterpret_cast<const ulonglong2*>(wp + WSTR);
            ulonglong2 wb1 = *reinterpret_cast<const ulonglong2*>(wp + WSTR + 4);
            ulonglong2 wc0 = *reinterpret_cast<const ulonglong2*>(wp + 2 * WSTR);
            ulonglong2 wc1 = *reinterpret_cast<const ulonglong2*>(wp + 2 * WSTR + 4);
            ulonglong2 wd0 = *reinterpret_cast<const ulonglong2*>(wp + 3 * WSTR);
            ulonglong2 wd1 = *reinterpret_cast<const ulonglong2*>(wp + 3 * WSTR + 4);
#pragma unroll
            for (int ki = 0; ki < 8; ki++) {
                float4 hv = *reinterpret_cast<const float4*>(hp2 + ki * HROWS + c);
                ull h0 = pk2(hv.x, hv.x);
                ull h1 = pk2(hv.y, hv.y);
                ull h2 = pk2(hv.z, hv.z);
                ull h3 = pk2(hv.w, hv.w);
                acc[ki][0] = fma2_(h0, wa0.x, acc[ki][0]);
                acc[ki][1] = fma2_(h0, wa0.y, acc[ki][1]);
                acc[ki][2] = fma2_(h0, wa1.x, acc[ki][2]);
                acc[ki][3] = fma2_(h0, wa1.y, acc[ki][3]);
                acc[ki][0] = fma2_(h1, wb0.x, acc[ki][0]);
                acc[ki][1] = fma2_(h1, wb0.y, acc[ki][1]);
                acc[ki][2] = fma2_(h1, wb1.x, acc[ki][2]);
                acc[ki][3] = fma2_(h1, wb1.y, acc[ki][3]);
                acc[ki][0] = fma2_(h2, wc0.x, acc[ki][0]);
                acc[ki][1] = fma2_(h2, wc0.y, acc[ki][1]);
                acc[ki][2] = fma2_(h2, wc1.x, acc[ki][2]);
                acc[ki][3] = fma2_(h2, wc1.y, acc[ki][3]);
                acc[ki][0] = fma2_(h3, wd0.x, acc[ki][0]);
                acc[ki][1] = fma2_(h3, wd0.y, acc[ki][1]);
                acc[ki][2] = fma2_(h3, wd1.x, acc[ki][2]);
                acc[ki][3] = fma2_(h3, wd1.y, acc[ki][3]);
            }
        }
    }

    __syncthreads();   // hs dead; pm aliases it

    {
        float mx[8];
#pragma unroll
        for (int j = 0; j < 8; j++) mx[j] = -CUDART_INF_F;
#pragma unroll
        for (int ki = 0; ki < 8; ki++) {
            float a0, a1, a2, a3, a4, a5, a6, a7;
            upk2(a0, a1, acc[ki][0]);
            upk2(a2, a3, acc[ki][1]);
            upk2(a4, a5, acc[ki][2]);
            upk2(a6, a7, acc[ki][3]);
            mx[0] = fmaxf(mx[0], leaky(a0));
            mx[1] = fmaxf(mx[1], leaky(a1));
            mx[2] = fmaxf(mx[2], leaky(a2));
            mx[3] = fmaxf(mx[3], leaky(a3));
            mx[4] = fmaxf(mx[4], leaky(a4));
            mx[5] = fmaxf(mx[5], leaky(a5));
            mx[6] = fmaxf(mx[6], leaky(a6));
            mx[7] = fmaxf(mx[7], leaky(a7));
        }
        float* pmp = pm + p * 128 + (k0 >> 3) * 64 + o0;
        *reinterpret_cast<float4*>(pmp)     = make_float4(mx[0], mx[1], mx[2], mx[3]);
        *reinterpret_cast<float4*>(pmp + 4) = make_float4(mx[4], mx[5], mx[6], mx[7]);
    }
    __syncthreads();

#pragma unroll
    for (int i = 0; i < 4; i++) {
        int ii = tid + i * 128;
        int pp = ii >> 6, oo = ii & 63;
        float mm = fmaxf(pm[pp * 128 + oo], pm[pp * 128 + 64 + oo]);
        int nn = blockIdx.x * 8 + pp;
        g_ms[((size_t)dirb * NPTS + nn) * CH + oo] = mm;
    }
}

// ---------------------------------------------------------------------------
// proj (R13): 128 threads = 128 output channels; weight row in registers,
// 64 points staged in smem, broadcast LDS.128 activations.
// ---------------------------------------------------------------------------
#define PPROJ 64
__global__ void __launch_bounds__(128) proj_kernel(
        const float* __restrict__ t1w, const float* __restrict__ t1b,
        const float* __restrict__ t2w, const float* __restrict__ t2b,
        float* __restrict__ out) {
    __shared__ float aS[PPROJ * 64];

    const int dir = blockIdx.z;
    const int b   = blockIdx.y;
    const int j   = threadIdx.x;
    const int dirb = dir * BATCH + b;

    const float* tw = dir ? t2w : t1w;
    const float* tb = dir ? t2b : t1b;

    float4 w[16];
#pragma unroll
    for (int t = 0; t < 16; t++)
        w[t] = reinterpret_cast<const float4*>(tw + j * 64)[t];
    const float bias = tb[j];

    const int n0 = blockIdx.x * PPROJ;
#pragma unroll
    for (int i = 0; i < PPROJ * 64 / 128 / 4; i++) {
        int f = j + i * 128;
        reinterpret_cast<float4*>(aS)[f] =
            reinterpret_cast<const float4*>(g_ms + ((size_t)dirb * NPTS + n0) * CH)[f];
    }
    __syncthreads();

#pragma unroll 2
    for (int p = 0; p < PPROJ; p++) {
        float acc = bias;
        const float4* ap = reinterpret_cast<const float4*>(aS + p * 64);
#pragma unroll
        for (int t = 0; t < 16; t++) {
            float4 a = ap[t];
            acc = fmaf(a.x, w[t].x, acc);
            acc = fmaf(a.y, w[t].y, acc);
            acc = fmaf(a.z, w[t].z, acc);
            acc = fmaf(a.w, w[t].w, acc);
        }
        out[((size_t)dirb * NPTS + n0 + p) * OUTCH + j] = acc;
    }
}

// ---------------------------------------------------------------------------
extern "C" void kernel_launch(void* const* d_in, const int* in_sizes, int n_in,
                              void* d_out, int out_size) {
    (void)in_sizes; (void)n_in; (void)out_size;
    const float* pc1   = (const float*)d_in[0];
    const float* pc2   = (const float*)d_in[1];
    const float* feat1 = (const float*)d_in[2];
    const float* feat2 = (const float*)d_in[3];
    const float* pos_w = (const float*)d_in[4];
    const float* pos_b = (const float*)d_in[5];
    const float* w0    = (const float*)d_in[6];
    const float* b0    = (const float*)d_in[7];
    const float* w1    = (const float*)d_in[8];
    const float* b1    = (const float*)d_in[9];
    const float* t1w   = (const float*)d_in[10];
    const float* t1b   = (const float*)d_in[11];
    const float* t2w   = (const float*)d_in[12];
    const float* t2b   = (const float*)d_in[13];
    float* out = (float*)d_out;

    pack_kernel<<<(2 * BATCH * NPTS + 255) / 256, 256>>>(pc1, pc2);
    wprep_kernel<<<4, 256>>>(w0, w1);

    // 64KB candidate tile + 8KB ushort slot-major idx = 72KB
    const size_t ksmem = 4 * SEGSZ * sizeof(float) + NSAMPLE * KBT * sizeof(ushort);
    cudaFuncSetAttribute(knn_kernel,
                         cudaFuncAttributeMaxDynamicSharedMemorySize, (int)ksmem);
    dim3 gk(NPTS / KBT, 2 * BATCH);
    knn_kernel<<<gk, KBT, ksmem>>>();

    const size_t smem = (size_t)(8 * HPNT + 192 + 64 * 3) * sizeof(float);
    cudaFuncSetAttribute(feat_kernel,
                         cudaFuncAttributeMaxDynamicSharedMemorySize, (int)smem);
    dim3 gf(NPTS / 8, BATCH, 2);
    feat_kernel<<<gf, 128, smem>>>(feat1, feat2, pos_w, pos_b, b0, b1);

    dim3 gp(NPTS / PPROJ, BATCH, 2);
    proj_kernel<<<gp, 128>>>(t1w, t1b, t2w, t2b, out);
}